// round 5
// baseline (speedup 1.0000x reference)
#include <cuda_runtime.h>
#include <cstdint>

// Problem dims (fixed by the reference).
#define Bq 128
#define Tq 64
#define Dq 256
#define Hq 256

#define GRID 128   // 2 layers x 64 tiles (8 m-tiles x 8 n-tiles of 16x32)
#define NTHR 128   // 4 warps: thread tile 2m x 2n
#define KC   64    // k-chunk, double buffered
#define NGRP 8     // one sync group per m-tile: 8 n-tiles x 2 layers = 16 CTAs
#define GMEM 16    // members per group

// ---------------- persistent state (device globals; no allocation) ----------
__device__ __align__(16) float g_h [2][Bq * Hq];   // current hidden per layer
__device__ __align__(16) float g_n0[2][Bq * Hq];   // node0 per layer
__device__ __align__(16) float g_n1[2][Bq * Hq];   // node1 per layer
__device__ __align__(128) unsigned int g_count[NGRP * 32];  // 1 counter / 128B

// ---------------- small helpers --------------------------------------------
__device__ __forceinline__ void cpa16(void* dst, const void* src) {
    unsigned s = (unsigned)__cvta_generic_to_shared(dst);
    asm volatile("cp.async.cg.shared.global [%0], [%1], 16;" :: "r"(s), "l"(src));
}
__device__ __forceinline__ void cpa_commit() { asm volatile("cp.async.commit_group;"); }
__device__ __forceinline__ void cpa_wait1()  { asm volatile("cp.async.wait_group 1;"); }
__device__ __forceinline__ void cpa_wait0()  { asm volatile("cp.async.wait_group 0;"); }

// Group barrier over the 16 CTAs that share an m-tile (all co-resident:
// GRID=128 <= 148 SMs, __launch_bounds__(NTHR,1), single wave).
// __syncthreads (CTA release) -> thread0 fence.gpu + atomicAdd (cumulative
// release) -> thread0 ld.acquire.gpu spin -> __syncthreads (CTA broadcast).
__device__ __forceinline__ void group_barrier(unsigned int* cnt, unsigned target) {
    __syncthreads();
    if (threadIdx.x == 0) {
        __threadfence();
        atomicAdd(cnt, 1u);
        unsigned v;
        do {
            asm volatile("ld.acquire.gpu.global.u32 %0, [%1];"
                         : "=r"(v) : "l"(cnt) : "memory");
        } while (v < target);
    }
    __syncthreads();
}

// ---------------- init kernel: reset barriers, seed hidden state ------------
__global__ void rnn_init(const float* __restrict__ hidden) {
    if (blockIdx.x == 0 && threadIdx.x < NGRP) g_count[threadIdx.x * 32] = 0u;
    int n = 2 * Bq * Hq;
    for (int i = blockIdx.x * blockDim.x + threadIdx.x; i < n;
         i += gridDim.x * blockDim.x)
        (&g_h[0][0])[i] = hidden[i];   // hidden is [L,B,H] = same contiguous layout
}

// ---------------- persistent wavefront kernel -------------------------------
__global__ void __launch_bounds__(NTHR, 1) rnn_persistent(
    const float* __restrict__ x,
    const float* __restrict__ Win0, const float* __restrict__ Wh0,
    const float* __restrict__ b0,
    const float* __restrict__ Win1, const float* __restrict__ Wh1,
    const float* __restrict__ b1,
    float* __restrict__ out)
{
    // A tile: 16 rows x KC (padded 68 floats: 272B rows, 16B-aligned for cp.async)
    // W tile: KC x 32 cols (padded 36 floats: 144B rows, 16B-aligned)
    __shared__ __align__(16) float As[2][16][68];
    __shared__ __align__(16) float Ws[2][KC][36];

    const int tid   = threadIdx.x;
    const int layer = blockIdx.x >> 6;          // 0 or 1
    const int tile  = blockIdx.x & 63;
    const int m0    = (tile >> 3) * 16;         // 8 m-tiles
    const int n0c   = (tile & 7)  * 32;         // 8 n-tiles
    const int tx2   = (tid & 15) * 2;           // 2 output columns
    const int ty2   = (tid >> 4) * 2;           // 2 output rows
    unsigned int* cnt = &g_count[(tile >> 3) * 32];  // group = m-tile (both layers)

    const float* Win = layer ? Win1 : Win0;
    const float* Wh  = layer ? Wh1  : Wh0;
    const float* bb  = layer ? b1   : b0;
    float* hbuf  = g_h[layer];
    float* n0buf = g_n0[layer];
    float* n1buf = g_n1[layer];

    unsigned bt = 0;

    // --- staging helpers (cooperative across the CTA) -----------------------
    auto stage_a = [&](int buf, const float* Abase, long arow, int kb) {
        #pragma unroll
        for (int j = tid; j < 256; j += NTHR) {              // A: 16 rows x 256B
            int row = j >> 4, seg = j & 15;
            cpa16(&As[buf][row][seg * 4], Abase + (long)row * arow + kb + seg * 4);
        }
    };
    auto stage_w = [&](int buf, const float* Wp, int kb) {
        #pragma unroll
        for (int j = tid; j < 512; j += NTHR) {              // W: KC rows x 128B
            int row = j >> 3, seg = j & 7;
            cpa16(&Ws[buf][row][seg * 4], Wp + (long)(kb + row) * Hq + seg * 4);
        }
    };
    // Prefetch W chunk-0 of the NEXT gemm into Ws[0] (own commit group). Safe:
    // Ws[0] was last read in the prior gemm's chunk c=2, which ended in a sync.
    auto prestage_w = [&](const float* Wp) { stage_w(0, Wp, 0); cpa_commit(); };

    // acc += A[16 x 256] @ W[256 x 32] restricted to this thread's 2x2 outputs.
    // A element [r][k] = Abase[r*arow + k]; W element [k][n] = Wp[k*Hq + n].
    // w0pre: W chunk-0 was already prestaged into Ws[0] before the barrier.
    auto gemm = [&](const float* Abase, long arow, const float* Wp,
                    float acc[4], bool w0pre) {
        stage_a(0, Abase, arow, 0);
        if (!w0pre) stage_w(0, Wp, 0);
        cpa_commit();
        #pragma unroll 1
        for (int c = 0; c < 4; ++c) {                        // K = 256 = 4 chunks
            if (c < 3) {
                int nb = (c + 1) & 1, kb = (c + 1) * KC;
                stage_a(nb, Abase, arow, kb);
                stage_w(nb, Wp, kb);
                cpa_commit();
                cpa_wait1();       // drains everything but the group just issued
            } else {
                cpa_wait0();
            }
            __syncthreads();
            const float (*Asb)[68] = As[c & 1];
            const float (*Wsb)[36] = Ws[c & 1];
            #pragma unroll 16
            for (int k = 0; k < KC; ++k) {
                float a0 = Asb[ty2][k];                      // broadcast over tx
                float a1 = Asb[ty2 + 1][k];
                float2 w = *(const float2*)&Wsb[k][tx2];     // conflict-free
                acc[0] = fmaf(a0, w.x, acc[0]);
                acc[1] = fmaf(a0, w.y, acc[1]);
                acc[2] = fmaf(a1, w.x, acc[2]);
                acc[3] = fmaf(a1, w.y, acc[3]);
            }
            __syncthreads();
        }
    };

    // Prestage W chunk-0 for iteration 0's phase A (layer0 only is active then).
    if (layer == 0)
        prestage_w(Win /* + t=0 offset = 0 */ + n0c);

    // Wavefront: iteration `it` runs layer0 step it and layer1 step it-1.
    // Dependencies are confined to the 16-CTA m-tile group:
    //   - column coupling within a layer-phase (8 n-tile CTAs)
    //   - layer0 -> layer1 handoff of the same rows (g_h[0], phase C -> phase A)
    for (int it = 0; it <= Tq; ++it) {
        const bool active = layer ? (it >= 1) : (it < Tq);
        const int  t      = layer ? (active ? it - 1 : 0) : (it < Tq ? it : 0);
        const float* Wh_t = Wh + (long)t * 3 * Hq * Hq;
        const float* b_t  = bb + (long)t * 3 * Hq;
        float n0r[4], n1r[4];

        // ---- phase A: n0 = tanh(x_t @ Win + h @ Wh[0] + b[0]) ----
        if (active) {
            float bA0 = __ldg(b_t + n0c + tx2);
            float bA1 = __ldg(b_t + n0c + tx2 + 1);
            float acc[4] = {0.f, 0.f, 0.f, 0.f};
            if (layer == 0)  // x: [B,T,D], row b at (b*T+t)*D, row stride T*D
                gemm(x + ((long)m0 * Tq + t) * Dq, (long)Tq * Dq,
                     Win + (long)t * Dq * Hq + n0c, acc, /*w0pre=*/true);
            else             // layer1 input = out0[t] = g_h[0] (pre-update this iter)
                gemm(g_h[0] + m0 * Hq, Hq, Win + (long)t * Hq * Hq + n0c, acc,
                     /*w0pre=*/true);
            gemm(hbuf + m0 * Hq, Hq, Wh_t + n0c, acc, /*w0pre=*/false);
            #pragma unroll
            for (int i = 0; i < 4; ++i) {
                int nn = i & 1, mm = i >> 1;
                float v = tanhf(acc[i] + (nn ? bA1 : bA0));
                n0r[i] = v;
                __stcg(&n0buf[(m0 + ty2 + mm) * Hq + n0c + tx2 + nn], v);
            }
            prestage_w(Wh_t + (long)Hq * Hq + n0c);          // phase B weights
        }
        bt += GMEM; group_barrier(cnt, bt);

        // ---- phase B: n1 = relu(n0 @ Wh[1] + b[1]) + n0 ----
        if (active) {
            float bB0 = __ldg(b_t + Hq + n0c + tx2);
            float bB1 = __ldg(b_t + Hq + n0c + tx2 + 1);
            float acc[4] = {0.f, 0.f, 0.f, 0.f};
            gemm(n0buf + m0 * Hq, Hq, Wh_t + (long)Hq * Hq + n0c, acc, true);
            #pragma unroll
            for (int i = 0; i < 4; ++i) {
                int nn = i & 1, mm = i >> 1;
                float v = fmaxf(acc[i] + (nn ? bB1 : bB0), 0.f) + n0r[i];
                n1r[i] = v;
                __stcg(&n1buf[(m0 + ty2 + mm) * Hq + n0c + tx2 + nn], v);
            }
            prestage_w(Wh_t + 2L * Hq * Hq + n0c);           // phase C weights
        }
        bt += GMEM; group_barrier(cnt, bt);

        // ---- phase C: n2 = sigmoid(n1 @ Wh[2] + b[2]) + n0; h = 0.5*(n1+n2) ----
        if (active) {
            float bC0 = __ldg(b_t + 2 * Hq + n0c + tx2);
            float bC1 = __ldg(b_t + 2 * Hq + n0c + tx2 + 1);
            float acc[4] = {0.f, 0.f, 0.f, 0.f};
            gemm(n1buf + m0 * Hq, Hq, Wh_t + 2L * Hq * Hq + n0c, acc, true);
            #pragma unroll
            for (int i = 0; i < 4; ++i) {
                int nn = i & 1, mm = i >> 1;
                int m = m0 + ty2 + mm, n = n0c + tx2 + nn;
                float v  = acc[i] + (nn ? bC1 : bC0);
                float n2 = 1.f / (1.f + expf(-v)) + n0r[i];
                float h  = 0.5f * (n1r[i] + n2);
                __stcg(&hbuf[m * Hq + n], h);
                if (layer == 1)                      // output[b][t][h], batch-first
                    out[((long)m * Tq + t) * Hq + n] = h;
                if (t == Tq - 1)                     // final hidden [L,B,H]
                    out[(long)Bq * Tq * Hq + (long)layer * Bq * Hq + m * Hq + n] = h;
            }
        }
        // Prestage next iteration's phase-A first-gemm weights.
        if (it < Tq) {
            if (layer == 0) {
                if (it + 1 < Tq)                     // layer0 next t = it+1
                    prestage_w(Win + (long)(it + 1) * Dq * Hq + n0c);
            } else {                                 // layer1 next t = it (always active)
                prestage_w(Win + (long)it * Hq * Hq + n0c);
            }
        }
        bt += GMEM; group_barrier(cnt, bt);
    }
}

// ---------------- entry point ----------------------------------------------
extern "C" void kernel_launch(void* const* d_in, const int* in_sizes, int n_in,
                              void* d_out, int out_size) {
    const float* x    = (const float*)d_in[0];
    const float* hid  = (const float*)d_in[1];
    const float* Win0 = (const float*)d_in[2];
    const float* Wh0  = (const float*)d_in[3];
    const float* b0   = (const float*)d_in[4];
    const float* Win1 = (const float*)d_in[5];
    const float* Wh1  = (const float*)d_in[6];
    const float* b1   = (const float*)d_in[7];
    float* out = (float*)d_out;

    rnn_init<<<64, 256>>>(hid);                       // resets barriers each replay
    rnn_persistent<<<GRID, NTHR>>>(x, Win0, Wh0, b0, Win1, Wh1, b1, out);
}

// round 7
// speedup vs baseline: 1.0473x; 1.0473x over previous
#include <cuda_runtime.h>
#include <cstdint>

// Problem dims (fixed by the reference).
#define Bq 128
#define Tq 64
#define Dq 256
#define Hq 256

#define GRID 128   // 2 layers x 64 tiles (8 m-tiles x 8 n-tiles of 16x32)
#define NTHR 256   // 8 warps: 2x2 thread tile, k split across thread halves
#define KC   64    // k-chunk, 3-slot ring buffer
#define NGRP 8     // one sync group per m-tile: 8 n-tiles x 2 layers = 16 CTAs
#define GMEM 16    // members per group

// ---------------- persistent state (device globals; no allocation) ----------
__device__ __align__(16) float g_h [2][Bq * Hq];   // current hidden per layer
__device__ __align__(16) float g_n0[2][Bq * Hq];   // node0 per layer
__device__ __align__(16) float g_n1[2][Bq * Hq];   // node1 per layer
__device__ __align__(128) unsigned int g_count[NGRP * 32];  // 1 counter / 128B

// ---------------- small helpers --------------------------------------------
__device__ __forceinline__ void cpa16(void* dst, const void* src) {
    unsigned s = (unsigned)__cvta_generic_to_shared(dst);
    asm volatile("cp.async.cg.shared.global [%0], [%1], 16;" :: "r"(s), "l"(src));
}
__device__ __forceinline__ void cpa_commit() { asm volatile("cp.async.commit_group;"); }
__device__ __forceinline__ void cpa_wait1()  { asm volatile("cp.async.wait_group 1;"); }
__device__ __forceinline__ void cpa_wait0()  { asm volatile("cp.async.wait_group 0;"); }

// Group barrier over the 16 CTAs that share an m-tile (all co-resident:
// GRID=128 <= 148 SMs, __launch_bounds__(NTHR,1), single wave).
__device__ __forceinline__ void group_barrier(unsigned int* cnt, unsigned target) {
    __syncthreads();
    if (threadIdx.x == 0) {
        __threadfence();
        atomicAdd(cnt, 1u);
        unsigned v;
        do {
            asm volatile("ld.acquire.gpu.global.u32 %0, [%1];"
                         : "=r"(v) : "l"(cnt) : "memory");
        } while (v < target);
    }
    __syncthreads();
}

// ---------------- init kernel: reset barriers, seed hidden state ------------
__global__ void rnn_init(const float* __restrict__ hidden) {
    if (blockIdx.x == 0 && threadIdx.x < NGRP) g_count[threadIdx.x * 32] = 0u;
    int n = 2 * Bq * Hq;
    for (int i = blockIdx.x * blockDim.x + threadIdx.x; i < n;
         i += gridDim.x * blockDim.x)
        (&g_h[0][0])[i] = hidden[i];   // hidden is [L,B,H] = same contiguous layout
}

// ---------------- persistent wavefront kernel -------------------------------
__global__ void __launch_bounds__(NTHR, 1) rnn_persistent(
    const float* __restrict__ x,
    const float* __restrict__ Win0, const float* __restrict__ Wh0,
    const float* __restrict__ b0,
    const float* __restrict__ Win1, const float* __restrict__ Wh1,
    const float* __restrict__ b1,
    float* __restrict__ out)
{
    // 3-slot ring. A: 16 rows x KC (pad 68); W: KC x 32 (pad 36). 16B-aligned rows.
    __shared__ __align__(16) float As[3][16][68];
    __shared__ __align__(16) float Ws[3][KC][36];
    __shared__ __align__(16) float4 red[NTHR];       // cross-half reduction

    const int tid   = threadIdx.x;
    const int htid  = tid & 127;                // index within k-half
    const int kb0   = (tid >> 7) * 32;          // this half's k-offset in a chunk
    const int layer = blockIdx.x >> 6;          // 0 or 1
    const int tile  = blockIdx.x & 63;
    const int m0    = (tile >> 3) * 16;         // 8 m-tiles
    const int n0c   = (tile & 7)  * 32;         // 8 n-tiles
    const int tx2   = (htid & 15) * 2;          // 2 output columns
    const int ty2   = (htid >> 4) * 2;          // 2 output rows
    unsigned int* cnt = &g_count[(tile >> 3) * 32];  // group = m-tile (both layers)

    const float* Win = layer ? Win1 : Win0;
    const float* Wh  = layer ? Wh1  : Wh0;
    const float* bb  = layer ? b1   : b0;
    float* hbuf  = g_h[layer];
    float* n0buf = g_n0[layer];
    float* n1buf = g_n1[layer];

    unsigned bt = 0;

    // --- staging (cooperative across all 256 threads) ------------------------
    auto stage_a = [&](int buf, const float* Abase, long arow) {
        int row = tid >> 4, seg = tid & 15;     // 16 rows x 16 segs -> 1/thread
        cpa16(&As[buf][row][seg * 4], Abase + (long)row * arow + seg * 4);
    };
    auto stage_w = [&](int buf, const float* Wp) {
        #pragma unroll
        for (int j = tid; j < 512; j += NTHR) { // KC rows x 128B -> 2/thread
            int row = j >> 3, seg = j & 7;
            cpa16(&Ws[buf][row][seg * 4], Wp + (long)row * Hq + seg * 4);
        }
    };
    // Prefetch W chunks 0,1 of the NEXT gemm into slots 0,1 as ONE group.
    // Issued after the gemm's reduce-sync: every thread's last read of Ws slots
    // 0/1 precedes that sync, so the write is WAR-safe.
    auto prestage_w = [&](const float* w0, const float* w1c) {
        stage_w(0, w0); stage_w(1, w1c); cpa_commit();
    };

    // acc += A[16 x n*64] @ W[n*64 x 32] for this thread's 2x2 outputs.
    // Two source segments (n1c + n2c chunks); k split across thread halves.
    // wpre: W for chunks 0,1 already staged as one pending group before entry.
    //
    // Pipeline invariant at iter c: pending groups (per thread, oldest first)
    // are {g_c, g_{c+1}} (plus prestage folded into the oldest at c=0), so
    // wait_group(1) drains exactly g_c; the following __syncthreads makes
    // chunk c visible CTA-wide before compute. Stage of chunk c+2 goes to
    // slot (c+2)%3 == (c-1)%3, whose readers (compute c-1) all finished
    // before this iteration's sync. Single sync per chunk, race-free.
    auto gemm = [&](const float* a1, long arow1, const float* w1p, int n1c,
                    const float* a2, long arow2, const float* w2p, int n2c,
                    float acc[4], bool wpre) {
        const int n = n1c + n2c;
        auto aofs = [&](int c) { return c < n1c ? a1 + (long)c * KC
                                                : a2 + (long)(c - n1c) * KC; };
        auto arw  = [&](int c) { return c < n1c ? arow1 : arow2; };
        auto wofs = [&](int c) { return c < n1c ? w1p + (long)c * KC * Hq
                                                : w2p + (long)(c - n1c) * KC * Hq; };
        stage_a(0, aofs(0), arw(0)); if (!wpre) stage_w(0, wofs(0)); cpa_commit();
        stage_a(1, aofs(1), arw(1)); if (!wpre) stage_w(1, wofs(1)); cpa_commit();
        #pragma unroll 1
        for (int c = 0; c < n; ++c) {
            if (c + 1 < n) cpa_wait1(); else cpa_wait0();
            __syncthreads();                    // chunk c visible CTA-wide
            const float (*Asb)[68] = As[c % 3];
            const float (*Wsb)[36] = Ws[c % 3];
            #pragma unroll
            for (int k = 0; k < 32; ++k) {      // this half's 32 of the 64 k's
                float a0  = Asb[ty2][kb0 + k];
                float a1v = Asb[ty2 + 1][kb0 + k];
                float2 w  = *(const float2*)&Wsb[kb0 + k][tx2];
                acc[0] = fmaf(a0,  w.x, acc[0]);
                acc[1] = fmaf(a0,  w.y, acc[1]);
                acc[2] = fmaf(a1v, w.x, acc[2]);
                acc[3] = fmaf(a1v, w.y, acc[3]);
            }
            if (c + 2 < n) {                    // refill slot (c+2)%3
                int s = (c + 2) % 3;
                stage_a(s, aofs(c + 2), arw(c + 2));
                stage_w(s, wofs(c + 2));
                cpa_commit();
            }
        }
        // Deterministic cross-half reduce; a+b == b+a so both halves agree.
        red[tid] = make_float4(acc[0], acc[1], acc[2], acc[3]);
        __syncthreads();
        float4 o = red[tid ^ 128];
        acc[0] += o.x; acc[1] += o.y; acc[2] += o.z; acc[3] += o.w;
    };

    // Prestage W chunks 0,1 for iteration 0's phase A (layer0 active first).
    if (layer == 0)
        prestage_w(Win + n0c, Win + (long)KC * Hq + n0c);

    // Wavefront: iteration `it` runs layer0 step it and layer1 step it-1.
    for (int it = 0; it <= Tq; ++it) {
        const bool active = layer ? (it >= 1) : (it < Tq);
        const int  t      = layer ? (active ? it - 1 : 0) : (it < Tq ? it : 0);
        const float* Wh_t = Wh + (long)t * 3 * Hq * Hq;
        const float* b_t  = bb + (long)t * 3 * Hq;
        float n0r[4], n1r[4];

        // ---- phase A: n0 = tanh(x_t @ Win + h @ Wh[0] + b[0])  (fused K=512) ----
        if (active) {
            float bA0 = __ldg(b_t + n0c + tx2);
            float bA1 = __ldg(b_t + n0c + tx2 + 1);
            float acc[4] = {0.f, 0.f, 0.f, 0.f};
            if (layer == 0)  // x: [B,T,D], row b at (b*T+t)*D, row stride T*D
                gemm(x + ((long)m0 * Tq + t) * Dq, (long)Tq * Dq,
                     Win + (long)t * Dq * Hq + n0c, 4,
                     hbuf + m0 * Hq, Hq, Wh_t + n0c, 4, acc, true);
            else             // layer1 input = out0[t] = g_h[0] (pre-update this iter)
                gemm(g_h[0] + m0 * Hq, Hq, Win + (long)t * Hq * Hq + n0c, 4,
                     hbuf + m0 * Hq, Hq, Wh_t + n0c, 4, acc, true);
            #pragma unroll
            for (int i = 0; i < 4; ++i) {
                int nn = i & 1, mm = i >> 1;
                float v = tanhf(acc[i] + (nn ? bA1 : bA0));
                n0r[i] = v;
                if (tid < 128)
                    __stcg(&n0buf[(m0 + ty2 + mm) * Hq + n0c + tx2 + nn], v);
            }
            const float* wB = Wh_t + (long)Hq * Hq + n0c;    // phase B weights
            prestage_w(wB, wB + (long)KC * Hq);
        }
        bt += GMEM; group_barrier(cnt, bt);

        // ---- phase B: n1 = relu(n0 @ Wh[1] + b[1]) + n0 ----
        if (active) {
            float bB0 = __ldg(b_t + Hq + n0c + tx2);
            float bB1 = __ldg(b_t + Hq + n0c + tx2 + 1);
            float acc[4] = {0.f, 0.f, 0.f, 0.f};
            gemm(n0buf + m0 * Hq, Hq, Wh_t + (long)Hq * Hq + n0c, 4,
                 nullptr, 0, nullptr, 0, acc, true);
            #pragma unroll
            for (int i = 0; i < 4; ++i) {
                int nn = i & 1, mm = i >> 1;
                float v = fmaxf(acc[i] + (nn ? bB1 : bB0), 0.f) + n0r[i];
                n1r[i] = v;
                if (tid < 128)
                    __stcg(&n1buf[(m0 + ty2 + mm) * Hq + n0c + tx2 + nn], v);
            }
            const float* wC = Wh_t + 2L * Hq * Hq + n0c;     // phase C weights
            prestage_w(wC, wC + (long)KC * Hq);
        }
        bt += GMEM; group_barrier(cnt, bt);

        // ---- phase C: n2 = sigmoid(n1 @ Wh[2] + b[2]) + n0; h = 0.5*(n1+n2) ----
        if (active) {
            float bC0 = __ldg(b_t + 2 * Hq + n0c + tx2);
            float bC1 = __ldg(b_t + 2 * Hq + n0c + tx2 + 1);
            float acc[4] = {0.f, 0.f, 0.f, 0.f};
            gemm(n1buf + m0 * Hq, Hq, Wh_t + 2L * Hq * Hq + n0c, 4,
                 nullptr, 0, nullptr, 0, acc, true);
            #pragma unroll
            for (int i = 0; i < 4; ++i) {
                int nn = i & 1, mm = i >> 1;
                int m = m0 + ty2 + mm, n = n0c + tx2 + nn;
                float v  = acc[i] + (nn ? bC1 : bC0);
                float n2 = 1.f / (1.f + expf(-v)) + n0r[i];
                float h  = 0.5f * (n1r[i] + n2);
                if (tid < 128) {
                    __stcg(&hbuf[m * Hq + n], h);
                    if (layer == 1)              // output[b][t][h], batch-first
                        out[((long)m * Tq + t) * Hq + n] = h;
                    if (t == Tq - 1)             // final hidden [L,B,H]
                        out[(long)Bq * Tq * Hq + (long)layer * Bq * Hq
                            + m * Hq + n] = h;
                }
            }
        }
        // Prestage next iteration's phase-A first-segment weights (Win).
        if (it < Tq) {
            if (layer == 0) {
                if (it + 1 < Tq) {
                    const float* wN = Win + (long)(it + 1) * Dq * Hq + n0c;
                    prestage_w(wN, wN + (long)KC * Hq);
                }
            } else {                             // layer1 next t = it
                const float* wN = Win + (long)it * Hq * Hq + n0c;
                prestage_w(wN, wN + (long)KC * Hq);
            }
        }
        bt += GMEM; group_barrier(cnt, bt);
    }
}

// ---------------- entry point ----------------------------------------------
extern "C" void kernel_launch(void* const* d_in, const int* in_sizes, int n_in,
                              void* d_out, int out_size) {
    const float* x    = (const float*)d_in[0];
    const float* hid  = (const float*)d_in[1];
    const float* Win0 = (const float*)d_in[2];
    const float* Wh0  = (const float*)d_in[3];
    const float* b0   = (const float*)d_in[4];
    const float* Win1 = (const float*)d_in[5];
    const float* Wh1  = (const float*)d_in[6];
    const float* b1   = (const float*)d_in[7];
    float* out = (float*)d_out;

    rnn_init<<<64, 256>>>(hid);                       // resets barriers each replay
    rnn_persistent<<<GRID, NTHR>>>(x, Win0, Wh0, b0, Win1, Wh1, b1, out);
}